// round 4
// baseline (speedup 1.0000x reference)
#include <cuda_runtime.h>
#include <cstdint>

// Identity (ifft(fft(x)).real == x within fp32 roundoff, rel_err ~1.3e-7).
// R3 established we're at the chip's aggregate LTS/HBM ceiling (~7.45 TB/s
// read+write) with an SM copy kernel. This round tests the copy-engine path:
// a cudaMemcpyAsync D2D captured as a graph memcpy node, which may run on
// the DMA engines instead of SMs. If the LTS cap is truly path-independent
// this is neutral; if CE pipelines better or the node replays cheaper, we
// shave a few us.

extern "C" void kernel_launch(void* const* d_in, const int* in_sizes, int n_in,
                              void* d_out, int out_size)
{
    const float* x = (const float*)d_in[0];
    float* out = (float*)d_out;
    size_t bytes = (size_t)in_sizes[0] * sizeof(float);  // 128 MB

    cudaMemcpyAsync(out, x, bytes, cudaMemcpyDeviceToDevice, 0);
}

// round 5
// speedup vs baseline: 1.0071x; 1.0071x over previous
#include <cuda_runtime.h>
#include <cstdint>

// Identity (ifft(fft(x)).real == x, rel_err ~1.3e-7 << 1e-3).
// Established: SM copy kernel hits ~7.45 TB/s aggregate (93% of HBM spec);
// CE memcpy path is slightly worse (45.1 vs 43.5 us). This round: unroll x8
// (deeper per-warp MLP, fewer/fatter waves: 4096 blocks), streaming hints on
// both sides, exact-divide guard-free fast path.

__global__ __launch_bounds__(256) void identity_copy_f4x8(
    const float4* __restrict__ in, float4* __restrict__ out, int n4)
{
    int base = blockIdx.x * (blockDim.x * 8) + threadIdx.x;
    const int s = blockDim.x;

    if (base + 7 * s < n4) {
        // 8 independent LDG.128 front-batched, then 8 STG.128.
        float4 v0 = __ldcs(in + base);
        float4 v1 = __ldcs(in + base + s);
        float4 v2 = __ldcs(in + base + 2 * s);
        float4 v3 = __ldcs(in + base + 3 * s);
        float4 v4 = __ldcs(in + base + 4 * s);
        float4 v5 = __ldcs(in + base + 5 * s);
        float4 v6 = __ldcs(in + base + 6 * s);
        float4 v7 = __ldcs(in + base + 7 * s);
        __stcs(out + base,         v0);
        __stcs(out + base + s,     v1);
        __stcs(out + base + 2 * s, v2);
        __stcs(out + base + 3 * s, v3);
        __stcs(out + base + 4 * s, v4);
        __stcs(out + base + 5 * s, v5);
        __stcs(out + base + 6 * s, v6);
        __stcs(out + base + 7 * s, v7);
    } else {
        #pragma unroll
        for (int k = 0; k < 8; k++) {
            int i = base + k * s;
            if (i < n4) __stcs(out + i, __ldcs(in + i));
        }
    }
}

__global__ __launch_bounds__(256) void identity_copy_tail(
    const float* __restrict__ in, float* __restrict__ out, int start, int n)
{
    int i = start + blockIdx.x * blockDim.x + threadIdx.x;
    if (i < n) out[i] = in[i];
}

extern "C" void kernel_launch(void* const* d_in, const int* in_sizes, int n_in,
                              void* d_out, int out_size)
{
    const float* x = (const float*)d_in[0];
    float* out = (float*)d_out;
    int n = in_sizes[0];           // 33,554,432

    int n4 = n / 4;                // 8,388,608 float4
    if (n4 > 0) {
        const int threads = 256;
        const int per_block = threads * 8;             // 2048 float4 / block
        int blocks = (n4 + per_block - 1) / per_block; // 4096
        identity_copy_f4x8<<<blocks, threads>>>(
            (const float4*)x, (float4*)out, n4);
    }
    int tail_start = n4 * 4;
    if (n - tail_start > 0) {
        identity_copy_tail<<<1, 256>>>(x, out, tail_start, n);
    }
}

// round 6
// speedup vs baseline: 1.0368x; 1.0294x over previous
#include <cuda_runtime.h>
#include <cstdint>

// Identity (ifft(fft(x)).real == x, rel_err ~1.3e-7 << 1e-3 tolerance).
// At the chip's path-independent LTS/HBM ceiling (~7.45 TB/s aggregate).
// Unroll U-curve measured: x1=37.9us, x4=36.0us, x8=37.8us (occ/reg cost).
// This round probes the untested x2 point: MLP=2 per thread, 16384 blocks,
// regs ~20 -> occupancy back near 90%, more warps each with 2 in-flight
// LDG.128. Streaming hints (.cs) on both sides (zero reuse).

__global__ __launch_bounds__(256) void identity_copy_f4x2(
    const float4* __restrict__ in, float4* __restrict__ out, int n4)
{
    int base = blockIdx.x * (blockDim.x * 2) + threadIdx.x;
    const int s = blockDim.x;

    if (base + s < n4) {
        float4 a = __ldcs(in + base);
        float4 b = __ldcs(in + base + s);
        __stcs(out + base,     a);
        __stcs(out + base + s, b);
    } else {
        #pragma unroll
        for (int k = 0; k < 2; k++) {
            int i = base + k * s;
            if (i < n4) __stcs(out + i, __ldcs(in + i));
        }
    }
}

__global__ __launch_bounds__(256) void identity_copy_tail(
    const float* __restrict__ in, float* __restrict__ out, int start, int n)
{
    int i = start + blockIdx.x * blockDim.x + threadIdx.x;
    if (i < n) out[i] = in[i];
}

extern "C" void kernel_launch(void* const* d_in, const int* in_sizes, int n_in,
                              void* d_out, int out_size)
{
    const float* x = (const float*)d_in[0];
    float* out = (float*)d_out;
    int n = in_sizes[0];           // 33,554,432

    int n4 = n / 4;                // 8,388,608 float4
    if (n4 > 0) {
        const int threads = 256;
        const int per_block = threads * 2;             // 512 float4 / block
        int blocks = (n4 + per_block - 1) / per_block; // 16384
        identity_copy_f4x2<<<blocks, threads>>>(
            (const float4*)x, (float4*)out, n4);
    }
    int tail_start = n4 * 4;
    if (n - tail_start > 0) {
        identity_copy_tail<<<1, 256>>>(x, out, tail_start, n);
    }
}